// round 2
// baseline (speedup 1.0000x reference)
#include <cuda_runtime.h>
#include <cuda_bf16.h>
#include <math.h>

// Problem constants
#define NQ 900
#define BB 8
#define DD 256
#define HH_ 8
#define DH 32
#define LL 4
#define PP 4
#define DFF 2048
#define SS 12240
#define M1 (NQ*BB)          // 7200 rows in (q,b) flattening
#define BH (BB*HH_)         // 64

// ---------------- scratch (static device globals; no runtime allocation) ----
__device__ float g_qk   [M1*DD];          // queries + pos emb        (q,b) rows
__device__ float g_qkv  [M1*3*DD];        // fused qkv proj           (q,b) rows
__device__ float g_q    [BH*NQ*DH];
__device__ float g_k    [BH*NQ*DH];
__device__ float g_v    [BH*NQ*DH];
__device__ float g_scores[(size_t)BH*NQ*NQ];   // 207 MB
__device__ float g_o    [M1*DD];          // attn output (q,b) rows
__device__ float g_sa   [M1*DD];
__device__ float g_q1   [M1*DD];          // after norm2
__device__ float g_qin  [M1*DD];          // q_in, (b,q) rows
__device__ float g_value[(size_t)BB*SS*DD];    // 100 MB
__device__ float g_offs [M1*DD];          // (b,q) rows
__device__ float g_aw   [M1*128];         // (b,q) rows
__device__ float g_ca   [M1*DD];          // sampled output, (b,q) rows
__device__ float g_ca2  [M1*DD];          // cout proj, (b,q) rows
__device__ float g_q2   [M1*DD];          // after norm1
__device__ float g_ffn  [M1*DFF];
__device__ float g_ffn2 [M1*DD];

// ---------------- elementwise add -------------------------------------------
__global__ void add2_kernel(const float* __restrict__ a, const float* __restrict__ b,
                            float* __restrict__ out, int n) {
    int i = blockIdx.x * blockDim.x + threadIdx.x;
    if (i < n) out[i] = a[i] + b[i];
}

// ---------------- generic tiled NT GEMM -------------------------------------
// C[m,n] = alpha * sum_k A[m,k]*B[n,k] + bias[n]   (optionally relu / row mask)
// batched over blockIdx.z via element strides sAz/sBz/sCz.
__global__ void __launch_bounds__(256)
gemm_nt(const float* __restrict__ A, int lda, long sAz,
        const float* __restrict__ Bm, int ldb, long sBz,
        float* __restrict__ C, int ldc, long sCz,
        const float* __restrict__ bias,
        int M, int N, int K, float alpha, int relu,
        const unsigned char* __restrict__ mask, int maskStride)
{
    const int BM = 128, BN = 128, BK = 16;
    __shared__ float As[BK][BM + 4];
    __shared__ float Bs[BK][BN + 4];

    int z = blockIdx.z;
    A  += (long)z * sAz;
    Bm += (long)z * sBz;
    C  += (long)z * sCz;

    int m0 = blockIdx.y * BM;
    int n0 = blockIdx.x * BN;
    int t  = threadIdx.x;
    int tm = t >> 4;      // 0..15
    int tn = t & 15;      // 0..15

    float acc[8][8];
#pragma unroll
    for (int i = 0; i < 8; i++)
#pragma unroll
        for (int j = 0; j < 8; j++) acc[i][j] = 0.f;

    for (int k0 = 0; k0 < K; k0 += BK) {
        // load A tile (BM x BK) -> As[k][m]
#pragma unroll
        for (int it = 0; it < 2; it++) {
            int li  = t + it * 256;
            int row = li >> 2;
            int kq  = (li & 3) * 4;
            int gm = m0 + row, gk = k0 + kq;
            float4 v = make_float4(0.f, 0.f, 0.f, 0.f);
            if (gm < M) {
                if (gk + 3 < K) {
                    v = *reinterpret_cast<const float4*>(&A[(long)gm * lda + gk]);
                } else {
                    float* vp = (float*)&v;
#pragma unroll
                    for (int j = 0; j < 4; j++)
                        if (gk + j < K) vp[j] = A[(long)gm * lda + gk + j];
                }
            }
            As[kq + 0][row] = v.x; As[kq + 1][row] = v.y;
            As[kq + 2][row] = v.z; As[kq + 3][row] = v.w;
        }
        // load B tile (BN x BK) -> Bs[k][n]
#pragma unroll
        for (int it = 0; it < 2; it++) {
            int li  = t + it * 256;
            int col = li >> 2;
            int kq  = (li & 3) * 4;
            int gn = n0 + col, gk = k0 + kq;
            float4 v = make_float4(0.f, 0.f, 0.f, 0.f);
            if (gn < N) {
                if (gk + 3 < K) {
                    v = *reinterpret_cast<const float4*>(&Bm[(long)gn * ldb + gk]);
                } else {
                    float* vp = (float*)&v;
#pragma unroll
                    for (int j = 0; j < 4; j++)
                        if (gk + j < K) vp[j] = Bm[(long)gn * ldb + gk + j];
                }
            }
            Bs[kq + 0][col] = v.x; Bs[kq + 1][col] = v.y;
            Bs[kq + 2][col] = v.z; Bs[kq + 3][col] = v.w;
        }
        __syncthreads();

#pragma unroll
        for (int k = 0; k < BK; k++) {
            float a[8], b[8];
#pragma unroll
            for (int i = 0; i < 8; i++) a[i] = As[k][tm + i * 16];
#pragma unroll
            for (int j = 0; j < 8; j++) b[j] = Bs[k][tn + j * 16];
#pragma unroll
            for (int i = 0; i < 8; i++)
#pragma unroll
                for (int j = 0; j < 8; j++) acc[i][j] += a[i] * b[j];
        }
        __syncthreads();
    }

#pragma unroll
    for (int i = 0; i < 8; i++) {
        int m = m0 + tm + i * 16;
        if (m >= M) continue;
        bool mz = (mask != nullptr) && mask[(long)z * maskStride + m];
#pragma unroll
        for (int j = 0; j < 8; j++) {
            int n = n0 + tn + j * 16;
            if (n >= N) continue;
            float vv = alpha * acc[i][j] + (bias ? bias[n] : 0.f);
            if (relu) vv = fmaxf(vv, 0.f);
            if (mz) vv = 0.f;
            C[(long)m * ldc + n] = vv;
        }
    }
}

// ---------------- permute qkv -> (b,h,n,dh) contiguous -----------------------
__global__ void permute_qkv_kernel(const float* __restrict__ qkv,
                                   float* __restrict__ q, float* __restrict__ k,
                                   float* __restrict__ v) {
    int id = blockIdx.x * blockDim.x + threadIdx.x;
    if (id >= BH * NQ * DH) return;
    int d  = id & 31;
    int n  = (id >> 5) % NQ;
    int bh = id / (NQ * DH);
    int b = bh >> 3, h = bh & 7;
    long src = (long)(n * BB + b) * (3 * DD) + h * DH + d;
    q[id] = qkv[src];
    k[id] = qkv[src + DD];
    v[id] = qkv[src + 2 * DD];
}

// ---------------- row softmax over 900 (warp per row, row in registers) ------
__global__ void softmax900_kernel(float* __restrict__ scores) {
    int wid  = blockIdx.x * 8 + (threadIdx.x >> 5);  // 57600 rows
    int lane = threadIdx.x & 31;
    float* p = scores + (size_t)wid * NQ;
    float v[29];
    float mx = -1e30f;
#pragma unroll
    for (int i = 0; i < 29; i++) {
        int idx = lane + i * 32;
        v[i] = (idx < NQ) ? p[idx] : -1e30f;
        mx = fmaxf(mx, v[i]);
    }
#pragma unroll
    for (int o = 16; o; o >>= 1) mx = fmaxf(mx, __shfl_xor_sync(0xffffffffu, mx, o));
    float s = 0.f;
#pragma unroll
    for (int i = 0; i < 29; i++) { v[i] = __expf(v[i] - mx); s += v[i]; }
#pragma unroll
    for (int o = 16; o; o >>= 1) s += __shfl_xor_sync(0xffffffffu, s, o);
    float inv = 1.f / s;
#pragma unroll
    for (int i = 0; i < 29; i++) {
        int idx = lane + i * 32;
        if (idx < NQ) p[idx] = v[i] * inv;
    }
}

// ---------------- o = attn @ V  (warp per (b,h,q), lane = channel) -----------
__global__ void attn_o_kernel(const float* __restrict__ scores,
                              const float* __restrict__ v,
                              float* __restrict__ o) {
    int wid  = blockIdx.x * 8 + (threadIdx.x >> 5);   // 57600 = 64*900
    int lane = threadIdx.x & 31;
    int bh = wid / NQ;
    int q  = wid - bh * NQ;
    const float* pr = scores + (size_t)wid * NQ;
    const float* vb = v + (long)bh * NQ * DH + lane;
    float acc = 0.f;
    for (int k = 0; k < NQ; k += 4) {
        float p0 = pr[k], p1 = pr[k + 1], p2 = pr[k + 2], p3 = pr[k + 3];
        acc += p0 * vb[(k + 0) * DH];
        acc += p1 * vb[(k + 1) * DH];
        acc += p2 * vb[(k + 2) * DH];
        acc += p3 * vb[(k + 3) * DH];
    }
    int b = bh >> 3, h = bh & 7;
    o[(long)(q * BB + b) * DD + h * DH + lane] = acc;
}

// ---------------- residual + layernorm (block per row of 256) ----------------
__global__ void residual_ln_kernel(const float* __restrict__ x,
                                   const float* __restrict__ r, int permute,
                                   const float* __restrict__ g,
                                   const float* __restrict__ bt,
                                   float* __restrict__ out) {
    __shared__ float sh[8];
    int row = blockIdx.x, t = threadIdx.x;
    int rrow = permute ? ((row & 7) * NQ + (row >> 3)) : row;
    float v = x[(long)row * DD + t] + r[(long)rrow * DD + t];

    float s = v;
#pragma unroll
    for (int o = 16; o; o >>= 1) s += __shfl_xor_sync(0xffffffffu, s, o);
    if ((t & 31) == 0) sh[t >> 5] = s;
    __syncthreads();
    float tot = 0.f;
#pragma unroll
    for (int i = 0; i < 8; i++) tot += sh[i];
    float mean = tot * (1.f / DD);
    float d = v - mean;
    __syncthreads();

    float s2 = d * d;
#pragma unroll
    for (int o = 16; o; o >>= 1) s2 += __shfl_xor_sync(0xffffffffu, s2, o);
    if ((t & 31) == 0) sh[t >> 5] = s2;
    __syncthreads();
    float tot2 = 0.f;
#pragma unroll
    for (int i = 0; i < 8; i++) tot2 += sh[i];
    float var = tot2 * (1.f / DD);

    out[(long)row * DD + t] = d * rsqrtf(var + 1e-5f) * g[t] + bt[t];
}

// ---------------- build q_in (b,q) rows from (q,b) rows ----------------------
__global__ void qin_kernel(const float* __restrict__ q1, const float* __restrict__ qpe,
                           float* __restrict__ out) {
    int id = blockIdx.x * blockDim.x + threadIdx.x;
    if (id >= M1 * DD) return;
    int c  = id & 255;
    int rr = id >> 8;           // b*900+q
    int b = rr / NQ;
    int q = rr - b * NQ;
    long src = (long)(q * BB + b) * DD + c;
    out[id] = q1[src] + qpe[src];
}

// ---------------- deformable bilinear sampler (warp per (b,q,h)) -------------
__global__ void deform_sample_kernel(const float* __restrict__ offs,
                                     const float* __restrict__ aw,
                                     const float* __restrict__ ref,
                                     const float* __restrict__ value,
                                     float* __restrict__ out) {
    int wid  = blockIdx.x * 8 + (threadIdx.x >> 5);   // 57600 = 8*900*8
    int lane = threadIdx.x & 31;
    int b   = wid / (NQ * HH_);
    int rem = wid - b * (NQ * HH_);
    int q = rem >> 3;
    int h = rem & 7;

    const float* rp = ref + (long)(q * BB + b) * 4;
    float rx = rp[0], ry = rp[1], rw = rp[2], rh = rp[3];

    const float* ab = aw + (long)(b * NQ + q) * 128 + h * 16;
    float w[16];
    float mx = -1e30f;
#pragma unroll
    for (int i = 0; i < 16; i++) { w[i] = ab[i]; mx = fmaxf(mx, w[i]); }
    float s = 0.f;
#pragma unroll
    for (int i = 0; i < 16; i++) { w[i] = __expf(w[i] - mx); s += w[i]; }
    float inv = 1.f / s;

    const float* ob = offs + (long)(b * NQ + q) * DD + h * 32;

    const int HHs[4] = {96, 48, 24, 12};
    const int WWs[4] = {96, 48, 24, 12};
    const int STs[4] = {0, 9216, 11520, 12096};

    float acc = 0.f;
#pragma unroll
    for (int l = 0; l < LL; l++) {
        int hh = HHs[l], wd = WWs[l], st = STs[l];
#pragma unroll
        for (int p = 0; p < PP; p++) {
            float ox = ob[l * 8 + p * 2 + 0];
            float oy = ob[l * 8 + p * 2 + 1];
            float locx = rx + ox * 0.125f * rw;
            float locy = ry + oy * 0.125f * rh;
            float x = locx * wd - 0.5f;
            float y = locy * hh - 0.5f;
            float xf = floorf(x), yf = floorf(y);
            float fx = x - xf, fy = y - yf;
            int x0 = (int)xf, y0 = (int)yf;
            float wt = w[l * 4 + p] * inv;

            float cw[4] = {(1.f - fx) * (1.f - fy), fx * (1.f - fy),
                           (1.f - fx) * fy,          fx * fy};
            int xs[4] = {x0, x0 + 1, x0, x0 + 1};
            int ys[4] = {y0, y0, y0 + 1, y0 + 1};
#pragma unroll
            for (int c = 0; c < 4; c++) {
                int xi = xs[c], yi = ys[c];
                if (xi >= 0 && xi < wd && yi >= 0 && yi < hh) {
                    long sidx = (long)(b * SS + st + yi * wd + xi) * DD + h * 32 + lane;
                    acc += wt * cw[c] * value[sidx];
                }
            }
        }
    }
    out[(long)(b * NQ + q) * DD + h * 32 + lane] = acc;
}

// ---------------- host launch -----------------------------------------------
static inline void* sym(const void* s) {
    void* p = nullptr;
    cudaGetSymbolAddress(&p, s);
    return p;
}

extern "C" void kernel_launch(void* const* d_in, const int* in_sizes, int n_in,
                              void* d_out, int out_size) {
    const float* queries = (const float*)d_in[0];
    const float* qpe     = (const float*)d_in[1];
    const float* refp    = (const float*)d_in[2];
    const float* memory  = (const float*)d_in[3];
    const unsigned char* mask = (const unsigned char*)d_in[4];
    // d_in[5] level_start_index, d_in[6] spatial_shapes: known constants
    const float* in_w   = (const float*)d_in[7];
    const float* in_b   = (const float*)d_in[8];
    const float* out_w  = (const float*)d_in[9];
    const float* out_b  = (const float*)d_in[10];
    const float* n1g = (const float*)d_in[11];
    const float* n1b = (const float*)d_in[12];
    const float* n2g = (const float*)d_in[13];
    const float* n2b = (const float*)d_in[14];
    const float* n3g = (const float*)d_in[15];
    const float* n3b = (const float*)d_in[16];
    const float* l1w = (const float*)d_in[17];
    const float* l1b = (const float*)d_in[18];
    const float* l2w = (const float*)d_in[19];
    const float* l2b = (const float*)d_in[20];
    const float* ofw = (const float*)d_in[21];
    const float* ofb = (const float*)d_in[22];
    const float* aww = (const float*)d_in[23];
    const float* awb = (const float*)d_in[24];
    const float* vlw = (const float*)d_in[25];
    const float* vlb = (const float*)d_in[26];
    const float* cow = (const float*)d_in[27];
    const float* cob = (const float*)d_in[28];

    float* p_qk    = (float*)sym(g_qk);
    float* p_qkv   = (float*)sym(g_qkv);
    float* p_q     = (float*)sym(g_q);
    float* p_k     = (float*)sym(g_k);
    float* p_v     = (float*)sym(g_v);
    float* p_sc    = (float*)sym(g_scores);
    float* p_o     = (float*)sym(g_o);
    float* p_sa    = (float*)sym(g_sa);
    float* p_q1    = (float*)sym(g_q1);
    float* p_qin   = (float*)sym(g_qin);
    float* p_val   = (float*)sym(g_value);
    float* p_offs  = (float*)sym(g_offs);
    float* p_aw    = (float*)sym(g_aw);
    float* p_ca    = (float*)sym(g_ca);
    float* p_ca2   = (float*)sym(g_ca2);
    float* p_q2    = (float*)sym(g_q2);
    float* p_ffn   = (float*)sym(g_ffn);
    float* p_ffn2  = (float*)sym(g_ffn2);

    const int n_qk = M1 * DD;

    // 1. qk = queries + pos emb
    add2_kernel<<<(n_qk + 255) / 256, 256>>>(queries, qpe, p_qk, n_qk);

    // 2. QK projection (first 512 rows of in_proj) on qk; V projection on queries
    gemm_nt<<<dim3(4, 57, 1), 256>>>(p_qk, DD, 0, in_w, DD, 0,
                                     p_qkv, 3 * DD, 0, in_b,
                                     M1, 512, DD, 1.f, 0, nullptr, 0);
    gemm_nt<<<dim3(2, 57, 1), 256>>>(queries, DD, 0, in_w + 512 * DD, DD, 0,
                                     p_qkv + 512, 3 * DD, 0, in_b + 512,
                                     M1, DD, DD, 1.f, 0, nullptr, 0);

    // 3. split/permute to (b,h,n,dh)
    permute_qkv_kernel<<<(BH * NQ * DH + 255) / 256, 256>>>(p_qkv, p_q, p_k, p_v);

    // 4. scores = Q @ K^T / sqrt(32), batched over 64 (b,h)
    gemm_nt<<<dim3(8, 8, BH), 256>>>(p_q, DH, (long)NQ * DH,
                                     p_k, DH, (long)NQ * DH,
                                     p_sc, NQ, (long)NQ * NQ, nullptr,
                                     NQ, NQ, DH, 0.17677669529663687f, 0, nullptr, 0);

    // 5. softmax rows
    softmax900_kernel<<<7200, 256>>>(p_sc);

    // 6. o = attn @ V  -> (q,b,d) rows
    attn_o_kernel<<<7200, 256>>>(p_sc, p_v, p_o);

    // 7. out projection
    gemm_nt<<<dim3(2, 57, 1), 256>>>(p_o, DD, 0, out_w, DD, 0,
                                     p_sa, DD, 0, out_b,
                                     M1, DD, DD, 1.f, 0, nullptr, 0);

    // 8. queries = LN(queries + sa)   [norm2]
    residual_ln_kernel<<<M1, 256>>>(queries, p_sa, 0, n2g, n2b, p_q1);

    // 9. q_in = (queries + qpe) transposed to (b,q) rows
    qin_kernel<<<(n_qk + 255) / 256, 256>>>(p_q1, qpe, p_qin);

    // 10. value = memory_bt @ val_w^T + val_b (masked), batched over b
    gemm_nt<<<dim3(2, 96, BB), 256>>>(memory, BB * DD, (long)DD,
                                      vlw, DD, 0,
                                      p_val, DD, (long)SS * DD, vlb,
                                      SS, DD, DD, 1.f, 0, mask, SS);

    // 11. offsets + attention-weight projections
    gemm_nt<<<dim3(2, 57, 1), 256>>>(p_qin, DD, 0, ofw, DD, 0,
                                     p_offs, DD, 0, ofb,
                                     M1, DD, DD, 1.f, 0, nullptr, 0);
    gemm_nt<<<dim3(1, 57, 1), 256>>>(p_qin, DD, 0, aww, DD, 0,
                                     p_aw, 128, 0, awb,
                                     M1, 128, DD, 1.f, 0, nullptr, 0);

    // 12. bilinear sampling + weighted sum
    deform_sample_kernel<<<7200, 256>>>(p_offs, p_aw, refp, p_val, p_ca);

    // 13. cout projection
    gemm_nt<<<dim3(2, 57, 1), 256>>>(p_ca, DD, 0, cow, DD, 0,
                                     p_ca2, DD, 0, cob,
                                     M1, DD, DD, 1.f, 0, nullptr, 0);

    // 14. queries = LN(q1 + ca^T)   [norm1]  (permuted residual rows)
    residual_ln_kernel<<<M1, 256>>>(p_q1, p_ca2, 1, n1g, n1b, p_q2);

    // 15. FFN
    gemm_nt<<<dim3(16, 57, 1), 256>>>(p_q2, DD, 0, l1w, DD, 0,
                                      p_ffn, DFF, 0, l1b,
                                      M1, DFF, DD, 1.f, 1, nullptr, 0);
    gemm_nt<<<dim3(2, 57, 1), 256>>>(p_ffn, DFF, 0, l2w, DFF, 0,
                                     p_ffn2, DD, 0, l2b,
                                     M1, DD, DFF, 1.f, 0, nullptr, 0);

    // 16. output = LN(q2 + ffn)   [norm3]
    residual_ln_kernel<<<M1, 256>>>(p_q2, p_ffn2, 0, n3g, n3b, (float*)d_out);
}

// round 4
// speedup vs baseline: 2.2033x; 2.2033x over previous
#include <cuda_runtime.h>
#include <cuda_bf16.h>
#include <math.h>

// Problem constants
#define NQ 900
#define BB 8
#define DD 256
#define HH_ 8
#define DH 32
#define LL 4
#define PP 4
#define DFF 2048
#define SS 12240
#define M1 (NQ*BB)          // 7200 rows in (q,b) flattening
#define BH (BB*HH_)         // 64

// ---------------- scratch (static device globals; no runtime allocation) ----
__device__ float g_qk   [M1*DD];
__device__ float g_qkv  [M1*3*DD];
__device__ float g_q    [BH*NQ*DH];
__device__ float g_k    [BH*NQ*DH];
__device__ float g_vt   [BH*DH*NQ];            // V transposed: [bh][dh][n]
__device__ float g_scores[(size_t)BH*NQ*NQ];   // 207 MB
__device__ float g_o    [M1*DD];               // attn out, (q,b) rows
__device__ float g_sa   [M1*DD];
__device__ float g_q1   [M1*DD];
__device__ float g_qin  [M1*DD];               // (b,q) rows
__device__ float g_value[(size_t)BB*SS*DD];    // 100 MB
__device__ float g_offs [M1*DD];
__device__ float g_aw   [M1*128];
__device__ float g_ca   [M1*DD];
__device__ float g_ca2  [M1*DD];
__device__ float g_q2   [M1*DD];
__device__ float g_ffn  [M1*DFF];
__device__ float g_ffn2 [M1*DD];

// ---------------- helpers ----------------------------------------------------
__device__ __forceinline__ unsigned f2tf(float x) {
    unsigned r;
    asm("cvt.rna.tf32.f32 %0, %1;" : "=r"(r) : "f"(x));
    return r;
}

// ---------------- elementwise add -------------------------------------------
__global__ void add2_kernel(const float* __restrict__ a, const float* __restrict__ b,
                            float* __restrict__ out, int n) {
    int i = blockIdx.x * blockDim.x + threadIdx.x;
    if (i < n) out[i] = a[i] + b[i];
}

// ---------------- tf32 tensor-core NT GEMM ----------------------------------
// C[m,n] = alpha * sum_k A[m,k]*B[n,k] + bias[n]   (optional relu / row mask)
// batched over blockIdx.z via element strides sAz/sBz/sCz.
// 128x128x32 tiles, 8 warps (2x4), each warp 64x32 via m16n8k8 tf32 mma.
__global__ void __launch_bounds__(256)
gemm_tf32(const float* __restrict__ A, int lda, long sAz,
          const float* __restrict__ Bm, int ldb, long sBz,
          float* __restrict__ C, int ldc, long sCz,
          const float* __restrict__ bias,
          int M, int N, int K, float alpha, int relu,
          const unsigned char* __restrict__ mask, int maskStride)
{
    const int BM = 128, BN = 128, BK = 32;
    __shared__ unsigned As[BM][BK + 4];
    __shared__ unsigned Bs[BN][BK + 4];

    int z = blockIdx.z;
    A  += (long)z * sAz;
    Bm += (long)z * sBz;
    C  += (long)z * sCz;

    int m0 = blockIdx.y * BM;
    int n0 = blockIdx.x * BN;
    int t    = threadIdx.x;
    int lane = t & 31;
    int wid  = t >> 5;
    int wm = wid >> 2;          // 0..1  -> 64-row slab
    int wn = wid & 3;           // 0..3  -> 32-col slab
    int gr  = lane >> 2;        // group id 0..7
    int tig = lane & 3;         // thread-in-group 0..3

    float acc[4][4][4];
#pragma unroll
    for (int i = 0; i < 4; i++)
#pragma unroll
        for (int j = 0; j < 4; j++)
#pragma unroll
            for (int c = 0; c < 4; c++) acc[i][j][c] = 0.f;

    for (int k0 = 0; k0 < K; k0 += BK) {
        // load A tile (BM x BK) into As[m][k], convert to tf32
#pragma unroll
        for (int it = 0; it < 4; it++) {
            int f   = t + it * 256;          // float4 index 0..1023
            int row = f >> 3;
            int kq  = (f & 7) * 4;
            int gm = m0 + row, gk = k0 + kq;
            float4 v = make_float4(0.f, 0.f, 0.f, 0.f);
            if (gm < M) {
                if (gk + 3 < K) {
                    v = *reinterpret_cast<const float4*>(&A[(long)gm * lda + gk]);
                } else {
                    float* vp = (float*)&v;
#pragma unroll
                    for (int j = 0; j < 4; j++)
                        if (gk + j < K) vp[j] = A[(long)gm * lda + gk + j];
                }
            }
            As[row][kq + 0] = f2tf(v.x); As[row][kq + 1] = f2tf(v.y);
            As[row][kq + 2] = f2tf(v.z); As[row][kq + 3] = f2tf(v.w);
        }
        // load B tile (BN x BK) into Bs[n][k]
#pragma unroll
        for (int it = 0; it < 4; it++) {
            int f   = t + it * 256;
            int row = f >> 3;
            int kq  = (f & 7) * 4;
            int gn = n0 + row, gk = k0 + kq;
            float4 v = make_float4(0.f, 0.f, 0.f, 0.f);
            if (gn < N) {
                if (gk + 3 < K) {
                    v = *reinterpret_cast<const float4*>(&Bm[(long)gn * ldb + gk]);
                } else {
                    float* vp = (float*)&v;
#pragma unroll
                    for (int j = 0; j < 4; j++)
                        if (gk + j < K) vp[j] = Bm[(long)gn * ldb + gk + j];
                }
            }
            Bs[row][kq + 0] = f2tf(v.x); Bs[row][kq + 1] = f2tf(v.y);
            Bs[row][kq + 2] = f2tf(v.z); Bs[row][kq + 3] = f2tf(v.w);
        }
        __syncthreads();

#pragma unroll
        for (int ks = 0; ks < 4; ks++) {
            int kb = ks * 8;
            unsigned af[4][4], bf[4][2];
#pragma unroll
            for (int mt = 0; mt < 4; mt++) {
                int r0 = wm * 64 + mt * 16 + gr;
                af[mt][0] = As[r0    ][kb + tig];
                af[mt][1] = As[r0 + 8][kb + tig];
                af[mt][2] = As[r0    ][kb + 4 + tig];
                af[mt][3] = As[r0 + 8][kb + 4 + tig];
            }
#pragma unroll
            for (int nt = 0; nt < 4; nt++) {
                int c0 = wn * 32 + nt * 8 + gr;
                bf[nt][0] = Bs[c0][kb + tig];
                bf[nt][1] = Bs[c0][kb + 4 + tig];
            }
#pragma unroll
            for (int mt = 0; mt < 4; mt++)
#pragma unroll
                for (int nt = 0; nt < 4; nt++) {
                    asm volatile(
                        "mma.sync.aligned.m16n8k8.row.col.f32.tf32.tf32.f32 "
                        "{%0,%1,%2,%3}, {%4,%5,%6,%7}, {%8,%9}, {%0,%1,%2,%3};"
                        : "+f"(acc[mt][nt][0]), "+f"(acc[mt][nt][1]),
                          "+f"(acc[mt][nt][2]), "+f"(acc[mt][nt][3])
                        : "r"(af[mt][0]), "r"(af[mt][1]),
                          "r"(af[mt][2]), "r"(af[mt][3]),
                          "r"(bf[nt][0]), "r"(bf[nt][1]));
                }
        }
        __syncthreads();
    }

    // epilogue
#pragma unroll
    for (int mt = 0; mt < 4; mt++) {
#pragma unroll
        for (int half = 0; half < 2; half++) {
            int m = m0 + wm * 64 + mt * 16 + gr + half * 8;
            if (m >= M) continue;
            bool mz = (mask != nullptr) && mask[(long)z * maskStride + m];
#pragma unroll
            for (int nt = 0; nt < 4; nt++) {
                int n = n0 + wn * 32 + nt * 8 + 2 * tig;
#pragma unroll
                for (int e = 0; e < 2; e++) {
                    int nn = n + e;
                    if (nn >= N) continue;
                    float vv = alpha * acc[mt][nt][half * 2 + e] +
                               (bias ? bias[nn] : 0.f);
                    if (relu) vv = fmaxf(vv, 0.f);
                    if (mz) vv = 0.f;
                    C[(long)m * ldc + nn] = vv;
                }
            }
        }
    }
}

// ---------------- permute qkv -> q,k (b,h,n,dh) and v^T (b,h,dh,n) -----------
__global__ void permute_qkv_kernel(const float* __restrict__ qkv,
                                   float* __restrict__ q, float* __restrict__ k,
                                   float* __restrict__ vt) {
    int id = blockIdx.x * blockDim.x + threadIdx.x;
    if (id >= BH * NQ * DH) return;
    // q,k: d fastest
    {
        int d  = id & 31;
        int n  = (id >> 5) % NQ;
        int bh = id / (NQ * DH);
        int b = bh >> 3, h = bh & 7;
        long src = (long)(n * BB + b) * (3 * DD) + h * DH + d;
        q[id] = qkv[src];
        k[id] = qkv[src + DD];
    }
    // vt: n fastest  ->  vt[bh][d][n]
    {
        int n  = id % NQ;
        int d  = (id / NQ) % DH;
        int bh = id / (NQ * DH);
        int b = bh >> 3, h = bh & 7;
        long src = (long)(n * BB + b) * (3 * DD) + 2 * DD + h * DH + d;
        vt[id] = qkv[src];
    }
}

// ---------------- row softmax over 900 (warp per row, row in registers) ------
__global__ void softmax900_kernel(float* __restrict__ scores) {
    int wid  = blockIdx.x * 8 + (threadIdx.x >> 5);
    int lane = threadIdx.x & 31;
    float* p = scores + (size_t)wid * NQ;
    float v[29];
    float mx = -1e30f;
#pragma unroll
    for (int i = 0; i < 29; i++) {
        int idx = lane + i * 32;
        v[i] = (idx < NQ) ? p[idx] : -1e30f;
        mx = fmaxf(mx, v[i]);
    }
#pragma unroll
    for (int o = 16; o; o >>= 1) mx = fmaxf(mx, __shfl_xor_sync(0xffffffffu, mx, o));
    float s = 0.f;
#pragma unroll
    for (int i = 0; i < 29; i++) { v[i] = __expf(v[i] - mx); s += v[i]; }
#pragma unroll
    for (int o = 16; o; o >>= 1) s += __shfl_xor_sync(0xffffffffu, s, o);
    float inv = 1.f / s;
#pragma unroll
    for (int i = 0; i < 29; i++) {
        int idx = lane + i * 32;
        if (idx < NQ) p[idx] = v[i] * inv;
    }
}

// ---------------- residual + layernorm (block per row of 256) ----------------
__global__ void residual_ln_kernel(const float* __restrict__ x,
                                   const float* __restrict__ r, int permute,
                                   const float* __restrict__ g,
                                   const float* __restrict__ bt,
                                   float* __restrict__ out) {
    __shared__ float sh[8];
    int row = blockIdx.x, t = threadIdx.x;
    int rrow = permute ? ((row & 7) * NQ + (row >> 3)) : row;
    float v = x[(long)row * DD + t] + r[(long)rrow * DD + t];

    float s = v;
#pragma unroll
    for (int o = 16; o; o >>= 1) s += __shfl_xor_sync(0xffffffffu, s, o);
    if ((t & 31) == 0) sh[t >> 5] = s;
    __syncthreads();
    float tot = 0.f;
#pragma unroll
    for (int i = 0; i < 8; i++) tot += sh[i];
    float mean = tot * (1.f / DD);
    float d = v - mean;
    __syncthreads();

    float s2 = d * d;
#pragma unroll
    for (int o = 16; o; o >>= 1) s2 += __shfl_xor_sync(0xffffffffu, s2, o);
    if ((t & 31) == 0) sh[t >> 5] = s2;
    __syncthreads();
    float tot2 = 0.f;
#pragma unroll
    for (int i = 0; i < 8; i++) tot2 += sh[i];
    float var = tot2 * (1.f / DD);

    out[(long)row * DD + t] = d * rsqrtf(var + 1e-5f) * g[t] + bt[t];
}

// ---------------- build q_in (b,q) rows from (q,b) rows ----------------------
__global__ void qin_kernel(const float* __restrict__ q1, const float* __restrict__ qpe,
                           float* __restrict__ out) {
    int id = blockIdx.x * blockDim.x + threadIdx.x;
    if (id >= M1 * DD) return;
    int c  = id & 255;
    int rr = id >> 8;
    int b = rr / NQ;
    int q = rr - b * NQ;
    long src = (long)(q * BB + b) * DD + c;
    out[id] = q1[src] + qpe[src];
}

// ---------------- deformable bilinear sampler (warp per (b,q,h)) -------------
__global__ void deform_sample_kernel(const float* __restrict__ offs,
                                     const float* __restrict__ aw,
                                     const float* __restrict__ ref,
                                     const float* __restrict__ value,
                                     float* __restrict__ out) {
    int wid  = blockIdx.x * 8 + (threadIdx.x >> 5);
    int lane = threadIdx.x & 31;
    int b   = wid / (NQ * HH_);
    int rem = wid - b * (NQ * HH_);
    int q = rem >> 3;
    int h = rem & 7;

    const float* rp = ref + (long)(q * BB + b) * 4;
    float rx = rp[0], ry = rp[1], rw = rp[2], rh = rp[3];

    const float* ab = aw + (long)(b * NQ + q) * 128 + h * 16;
    float w[16];
    float mx = -1e30f;
#pragma unroll
    for (int i = 0; i < 16; i++) { w[i] = ab[i]; mx = fmaxf(mx, w[i]); }
    float s = 0.f;
#pragma unroll
    for (int i = 0; i < 16; i++) { w[i] = __expf(w[i] - mx); s += w[i]; }
    float inv = 1.f / s;

    const float* ob = offs + (long)(b * NQ + q) * DD + h * 32;

    const int HHs[4] = {96, 48, 24, 12};
    const int WWs[4] = {96, 48, 24, 12};
    const int STs[4] = {0, 9216, 11520, 12096};

    float acc = 0.f;
#pragma unroll
    for (int l = 0; l < LL; l++) {
        int hh = HHs[l], wd = WWs[l], st = STs[l];
#pragma unroll
        for (int p = 0; p < PP; p++) {
            float ox = ob[l * 8 + p * 2 + 0];
            float oy = ob[l * 8 + p * 2 + 1];
            float locx = rx + ox * 0.125f * rw;
            float locy = ry + oy * 0.125f * rh;
            float x = locx * wd - 0.5f;
            float y = locy * hh - 0.5f;
            float xf = floorf(x), yf = floorf(y);
            float fx = x - xf, fy = y - yf;
            int x0 = (int)xf, y0 = (int)yf;
            float wt = w[l * 4 + p] * inv;

            float cw[4] = {(1.f - fx) * (1.f - fy), fx * (1.f - fy),
                           (1.f - fx) * fy,          fx * fy};
            int xs[4] = {x0, x0 + 1, x0, x0 + 1};
            int ys[4] = {y0, y0, y0 + 1, y0 + 1};
#pragma unroll
            for (int c = 0; c < 4; c++) {
                int xi = xs[c], yi = ys[c];
                if (xi >= 0 && xi < wd && yi >= 0 && yi < hh) {
                    long sidx = (long)(b * SS + st + yi * wd + xi) * DD + h * 32 + lane;
                    acc += wt * cw[c] * value[sidx];
                }
            }
        }
    }
    out[(long)(b * NQ + q) * DD + h * 32 + lane] = acc;
}

// ---------------- host launch -----------------------------------------------
static inline void* sym(const void* s) {
    void* p = nullptr;
    cudaGetSymbolAddress(&p, s);
    return p;
}

extern "C" void kernel_launch(void* const* d_in, const int* in_sizes, int n_in,
                              void* d_out, int out_size) {
    const float* queries = (const float*)d_in[0];
    const float* qpe     = (const float*)d_in[1];
    const float* refp    = (const float*)d_in[2];
    const float* memory  = (const float*)d_in[3];
    const unsigned char* mask = (const unsigned char*)d_in[4];
    const float* in_w   = (const float*)d_in[7];
    const float* in_b   = (const float*)d_in[8];
    const float* out_w  = (const float*)d_in[9];
    const float* out_b  = (const float*)d_in[10];
    const float* n1g = (const float*)d_in[11];
    const float* n1b = (const float*)d_in[12];
    const float* n2g = (const float*)d_in[13];
    const float* n2b = (const float*)d_in[14];
    const float* n3g = (const float*)d_in[15];
    const float* n3b = (const float*)d_in[16];
    const float* l1w = (const float*)d_in[17];
    const float* l1b = (const float*)d_in[18];
    const float* l2w = (const float*)d_in[19];
    const float* l2b = (const float*)d_in[20];
    const float* ofw = (const float*)d_in[21];
    const float* ofb = (const float*)d_in[22];
    const float* aww = (const float*)d_in[23];
    const float* awb = (const float*)d_in[24];
    const float* vlw = (const float*)d_in[25];
    const float* vlb = (const float*)d_in[26];
    const float* cow = (const float*)d_in[27];
    const float* cob = (const float*)d_in[28];

    float* p_qk    = (float*)sym(g_qk);
    float* p_qkv   = (float*)sym(g_qkv);
    float* p_q     = (float*)sym(g_q);
    float* p_k     = (float*)sym(g_k);
    float* p_vt    = (float*)sym(g_vt);
    float* p_sc    = (float*)sym(g_scores);
    float* p_o     = (float*)sym(g_o);
    float* p_sa    = (float*)sym(g_sa);
    float* p_q1    = (float*)sym(g_q1);
    float* p_qin   = (float*)sym(g_qin);
    float* p_val   = (float*)sym(g_value);
    float* p_offs  = (float*)sym(g_offs);
    float* p_aw    = (float*)sym(g_aw);
    float* p_ca    = (float*)sym(g_ca);
    float* p_ca2   = (float*)sym(g_ca2);
    float* p_q2    = (float*)sym(g_q2);
    float* p_ffn   = (float*)sym(g_ffn);
    float* p_ffn2  = (float*)sym(g_ffn2);

    const int n_qk = M1 * DD;

    // 1. qk = queries + pos emb
    add2_kernel<<<(n_qk + 255) / 256, 256>>>(queries, qpe, p_qk, n_qk);

    // 2. QK projection on qk; V projection on queries
    gemm_tf32<<<dim3(4, 57, 1), 256>>>(p_qk, DD, 0, in_w, DD, 0,
                                       p_qkv, 3 * DD, 0, in_b,
                                       M1, 512, DD, 1.f, 0, nullptr, 0);
    gemm_tf32<<<dim3(2, 57, 1), 256>>>(queries, DD, 0, in_w + 512 * DD, DD, 0,
                                       p_qkv + 512, 3 * DD, 0, in_b + 512,
                                       M1, DD, DD, 1.f, 0, nullptr, 0);

    // 3. split/permute to (b,h,n,dh) for q,k and (b,h,dh,n) for v
    permute_qkv_kernel<<<(BH * NQ * DH + 255) / 256, 256>>>(p_qkv, p_q, p_k, p_vt);

    // 4. scores = Q @ K^T / sqrt(32), batched over 64 (b,h)
    gemm_tf32<<<dim3(8, 8, BH), 256>>>(p_q, DH, (long)NQ * DH,
                                       p_k, DH, (long)NQ * DH,
                                       p_sc, NQ, (long)NQ * NQ, nullptr,
                                       NQ, NQ, DH, 0.17677669529663687f, 0, nullptr, 0);

    // 5. softmax rows
    softmax900_kernel<<<7200, 256>>>(p_sc);

    // 6. o = attn @ V as batched NT GEMM: C[q, d] = sum_k P[q,k] * Vt[d,k]
    //    writes straight into (q,b,h,d) layout: ldc=2048, z-stride=32
    gemm_tf32<<<dim3(1, 8, BH), 256>>>(p_sc, NQ, (long)NQ * NQ,
                                       p_vt, NQ, (long)DH * NQ,
                                       p_o, BB * DD, 32L, nullptr,
                                       NQ, DH, NQ, 1.f, 0, nullptr, 0);

    // 7. out projection
    gemm_tf32<<<dim3(2, 57, 1), 256>>>(p_o, DD, 0, out_w, DD, 0,
                                       p_sa, DD, 0, out_b,
                                       M1, DD, DD, 1.f, 0, nullptr, 0);

    // 8. queries = LN(queries + sa)   [norm2]
    residual_ln_kernel<<<M1, 256>>>(queries, p_sa, 0, n2g, n2b, p_q1);

    // 9. q_in = (queries + qpe) transposed to (b,q) rows
    qin_kernel<<<(n_qk + 255) / 256, 256>>>(p_q1, qpe, p_qin);

    // 10. value = memory_bt @ val_w^T + val_b (masked), batched over b
    gemm_tf32<<<dim3(2, 96, BB), 256>>>(memory, BB * DD, (long)DD,
                                        vlw, DD, 0,
                                        p_val, DD, (long)SS * DD, vlb,
                                        SS, DD, DD, 1.f, 0, mask, SS);

    // 11. offsets + attention-weight projections
    gemm_tf32<<<dim3(2, 57, 1), 256>>>(p_qin, DD, 0, ofw, DD, 0,
                                       p_offs, DD, 0, ofb,
                                       M1, DD, DD, 1.f, 0, nullptr, 0);
    gemm_tf32<<<dim3(1, 57, 1), 256>>>(p_qin, DD, 0, aww, DD, 0,
                                       p_aw, 128, 0, awb,
                                       M1, 128, DD, 1.f, 0, nullptr, 0);

    // 12. bilinear sampling + weighted sum
    deform_sample_kernel<<<7200, 256>>>(p_offs, p_aw, refp, p_val, p_ca);

    // 13. cout projection
    gemm_tf32<<<dim3(2, 57, 1), 256>>>(p_ca, DD, 0, cow, DD, 0,
                                       p_ca2, DD, 0, cob,
                                       M1, DD, DD, 1.f, 0, nullptr, 0);

    // 14. queries = LN(q1 + ca^T)   [norm1]
    residual_ln_kernel<<<M1, 256>>>(p_q1, p_ca2, 1, n1g, n1b, p_q2);

    // 15. FFN
    gemm_tf32<<<dim3(16, 57, 1), 256>>>(p_q2, DD, 0, l1w, DD, 0,
                                        p_ffn, DFF, 0, l1b,
                                        M1, DFF, DD, 1.f, 1, nullptr, 0);
    gemm_tf32<<<dim3(2, 57, 1), 256>>>(p_ffn, DFF, 0, l2w, DFF, 0,
                                       p_ffn2, DD, 0, l2b,
                                       M1, DD, DFF, 1.f, 0, nullptr, 0);

    // 16. output = LN(q2 + ffn)   [norm3]
    residual_ln_kernel<<<M1, 256>>>(p_q2, p_ffn2, 0, n3g, n3b, (float*)d_out);
}